// round 14
// baseline (speedup 1.0000x reference)
#include <cuda_runtime.h>

#define NN   50000
#define C    128
#define E    800000
#define EF   65
#define EAC  70
#define ET   64

typedef unsigned long long ull;

// ---------------- scratch (device globals; no allocation allowed) ------------
__device__ float g_A [C*C];           // Wf1 + Wf3
__device__ float g_B [C*C];           // Wf2 - Wf3
__device__ float g_M [C*C];           // scale * Wq diag(Wa) Wk^T
__device__ float g_XA[NN*C];          // x @ A
__device__ float g_XB[NN*C];          // x @ B
__device__ float g_Xm[NN*C];          // x @ M
__device__ float g_asum[NN];          // segment sum of a over src
__device__ float g_aggr[NN*C];        // segment sum of exp(a)*f over src

// ---------------- packed fp32x2 helpers (Blackwell FFMA2) --------------------
__device__ __forceinline__ void fma2(ull &acc, ull a, ull b) {
    asm("fma.rn.f32x2 %0, %1, %2, %0;" : "+l"(acc) : "l"(a), "l"(b));
}
__device__ __forceinline__ ull dup2(float v) {
    unsigned int u = __float_as_uint(v);
    return ((ull)u << 32) | (ull)u;
}
__device__ __forceinline__ ull pack2(float x, float y) {
    return ((ull)__float_as_uint(y) << 32) | (ull)__float_as_uint(x);
}
__device__ __forceinline__ float2 unpack2(ull p) {
    float2 r;
    r.x = __uint_as_float((unsigned int)(p & 0xffffffffull));
    r.y = __uint_as_float((unsigned int)(p >> 32));
    return r;
}
// tanh via exp, saturates correctly at +-1
__device__ __forceinline__ float tanh_fast(float x) {
    float t = __expf(2.0f * x);
    return 1.0f - __fdividef(2.0f, t + 1.0f);
}

// ---------------- K0: fold weights ------------------------------------------
__global__ void prep_kernel(const float* __restrict__ Wf, const float* __restrict__ Wq,
                            const float* __restrict__ Wk, const float* __restrict__ Wa) {
    int d = blockIdx.x;      // 0..127
    int c = threadIdx.x;     // 0..127
    g_A[d*C + c] = Wf[d*C + c]        + Wf[(256+d)*C + c];
    g_B[d*C + c] = Wf[(128+d)*C + c]  - Wf[(256+d)*C + c];
    __shared__ float sWa[C], sWq[C];
    sWa[c] = Wa[c];
    sWq[c] = Wq[d*C + c];
    __syncthreads();
    float acc = 0.0f;
    #pragma unroll 4
    for (int k = 0; k < C; k++) acc += sWq[k] * sWa[k] * Wk[c*C + k];
    g_M[d*C + c] = acc * 0.08838834764831845f;   // 128^-0.5
}

// ============ K-split node-GEMM scheme ========================================
//   sW4  [64][32] float4 @ 0      32768 B
//   sXf  [64][33] f32    @ 32768   8448 B
//   sDsc [32] f32        @ 41216    128 B   (node_out: per-node exp(-asum))
#define NODE_SW   0
#define NODE_SX   32768
#define NODE_SD   41216
#define NODE_SMEM 41344

__device__ __forceinline__ void node_gemm_half(const float* sXf, const ulonglong2* sWu2,
                                               int lane, int nb, ull a0[4], ull a1[4]) {
    #pragma unroll 8
    for (int d = 0; d < 64; d++) {
        ulonglong2 wv = sWu2[d*32 + lane];
        #pragma unroll
        for (int e = 0; e < 4; e++) {
            ull xv = dup2(sXf[d*33 + nb + e]);
            fma2(a0[e], xv, wv.x);
            fma2(a1[e], xv, wv.y);
        }
    }
}

// ---------------- K1: node precompute XA, XB, Xm (+ zero fold) ---------------
__global__ __launch_bounds__(256, 5) void node_pre_kernel(const float* __restrict__ x) {
    extern __shared__ unsigned char smem[];
    float4*     sW4  = (float4*)(smem + NODE_SW);
    ulonglong2* sWu2 = (ulonglong2*)(smem + NODE_SW);
    float*      sXf  = (float*)(smem + NODE_SX);
    int tid = threadIdx.x, lane = tid & 31, w = tid >> 5;

    // folded zero of the accumulators (no sync needed; consumed next kernel)
    {
        float4 z; z.x = 0.0f; z.y = 0.0f; z.z = 0.0f; z.w = 0.0f;
        for (int i = blockIdx.x*256 + tid; i < NN*C/4; i += gridDim.x*256)
            ((float4*)g_aggr)[i] = z;
        for (int i = blockIdx.x*256 + tid; i < NN; i += gridDim.x*256)
            g_asum[i] = 0.0f;
    }

    const float* Ws[3] = {g_A, g_B, g_M};
    float*       Ys[3] = {g_XA, g_XB, g_Xm};
    const int ntiles = (NN + 31) / 32;
    for (int m = 0; m < 3; m++) {
        const float4* W4 = (const float4*)Ws[m];
        float* Y = Ys[m];
        for (int h = 0; h < 2; h++) {
            __syncthreads();
            for (int i = tid; i < 64*32; i += 256) {
                int dd = i >> 5, l = i & 31;
                sW4[i] = W4[(h*64 + dd)*32 + l];
            }
            for (int tile = blockIdx.x; tile < ntiles; tile += gridDim.x) {
                int n0 = tile * 32;
                __syncthreads();
                for (int i = tid; i < 64*32; i += 256) {
                    int d = i & 63, n = i >> 6, ng = n0 + n;
                    sXf[d*33 + n] = (ng < NN) ? x[(size_t)ng*C + h*64 + d] : 0.0f;
                }
                __syncthreads();
                int nb = w * 4;
                ull a0[4] = {0,0,0,0}, a1[4] = {0,0,0,0};
                node_gemm_half(sXf, sWu2, lane, nb, a0, a1);
                #pragma unroll 1
                for (int e = 0; e < 4; e++) {
                    int n = n0 + nb + e;
                    if (n < NN) {
                        float2 f0 = unpack2(a0[e]), f1 = unpack2(a1[e]);
                        float4 o; o.x = f0.x; o.y = f0.y; o.z = f1.x; o.w = f1.y;
                        float* yp = Y + (size_t)n*C + 4*lane;
                        if (h) {
                            float4 prev = *(float4*)yp;
                            o.x += prev.x; o.y += prev.y; o.z += prev.z; o.w += prev.w;
                        }
                        *(float4*)yp = o;
                    }
                }
            }
        }
    }
}

// ---------------- K2: edge pass — f, a, scatter exp(a)*f and a ----------------
// 256 thr (8 warps), 64 edges/tile, warp = 8 edges (4 edge-pairs) x 128 ch.
//   sW4  [65][32] float4  @ 0      33280 B
//   sEa  [65][66] float   @ 33280  17160 B  (u64 col p = edge pair {2p,2p+1})
//   sBf4 [32]  float4     @ 50448    512 B
//   sIdx [128] int        @ 50960    512 B
#define E1_SW   0
#define E1_SEA  33280
#define E1_SBF  50448
#define E1_SIDX 50960
#define E1_SMEM 51472

__global__ __launch_bounds__(256, 4) void edge1_kernel(const float* __restrict__ ea,
                                                       const int*   __restrict__ ei,
                                                       const float* __restrict__ Wf,
                                                       const float* __restrict__ bf) {
    extern __shared__ unsigned char smem[];
    float4*     sW4  = (float4*)(smem + E1_SW);
    ull*        sEa2 = (ull*)(smem + E1_SEA);
    float*      sEaF = (float*)(smem + E1_SEA);
    float4*     sBf4 = (float4*)(smem + E1_SBF);
    int*        sIdx = (int*)(smem + E1_SIDX);
    int tid = threadIdx.x, lane = tid & 31, w = tid >> 5;

    for (int i = tid; i < EF*32; i += 256) {
        int d = i >> 5, l = i & 31;
        sW4[i] = *(const float4*)(Wf + (size_t)(3*C + d)*C + 4*l);
    }
    if (tid < 32) sBf4[tid] = *(const float4*)(bf + 4*tid);
    __syncthreads();
    float4 b4 = sBf4[lane];
    ull bi0 = dup2(b4.x), bi1 = dup2(b4.y), bi2 = dup2(b4.z), bi3 = dup2(b4.w);

    const int eb = w * 8;                 // this warp's 8 edges within the tile
    const int pb = w * 4;                 // this warp's 4 edge-pairs
    const int ntiles = E / ET;            // 12500
    for (int tile = blockIdx.x; tile < ntiles; tile += gridDim.x) {
        int e0 = tile * ET;
        __syncthreads();
        if (tid < ET)           sIdx[tid] = ei[e0 + tid];
        else if (tid < 2*ET)    sIdx[tid] = ei[E + e0 + tid - ET];
        // coalesced ea staging; lane l writes rows (l, l+32): word-stride 66
        // => 2-way STS bank conflict
        #pragma unroll 1
        for (int i = 0; i < 8; i++) {
            int e = eb + i;
            const float* row = ea + (size_t)(e0 + e)*EAC;
            float vx = __ldcs(row + lane);
            float vy = __ldcs(row + lane + 32);
            sEaF[lane*66        + e] = vx;
            sEaF[(lane + 32)*66 + e] = vy;
            if (lane == 0) sEaF[64*66 + e] = __ldcs(row + 64);
        }
        __syncthreads();

        // GEMM: acc[c][p] = f32x2 accumulator for channel 4*lane+c, edge pair p
        ull a0[4], a1[4], a2[4], a3[4];
        #pragma unroll
        for (int p = 0; p < 4; p++) { a0[p]=bi0; a1[p]=bi1; a2[p]=bi2; a3[p]=bi3; }
        #pragma unroll 5
        for (int d = 0; d < EF; d++) {
            float4 wv = sW4[d*32 + lane];
            ull w0 = dup2(wv.x), w1 = dup2(wv.y), w2 = dup2(wv.z), w3 = dup2(wv.w);
            const ull* er = sEa2 + d*33 + pb;
            #pragma unroll
            for (int p = 0; p < 4; p++) {
                ull ep = er[p];                  // LDS.64 broadcast
                fma2(a0[p], ep, w0);
                fma2(a1[p], ep, w1);
                fma2(a2[p], ep, w2);
                fma2(a3[p], ep, w3);
            }
        }

        // ---- batched epilogue: 2 groups of 4 edges --------------------------
        #pragma unroll
        for (int g = 0; g < 2; g++) {
            float fv[4][4];
            float pd[4];
            int   sg[4];
            #pragma unroll
            for (int i = 0; i < 4; i++) {
                int e = eb + g*4 + i;
                int p = (g*4 + i) >> 1, par = i & 1;
                int s = sIdx[e], t = sIdx[ET + e];
                sg[i] = s;
                float4 xa = __ldg((const float4*)(g_XA + (size_t)s*C + 4*lane));
                float4 xb = __ldg((const float4*)(g_XB + (size_t)t*C + 4*lane));
                float4 xm = __ldg((const float4*)(g_Xm + (size_t)s*C + 4*lane));
                float2 c0 = unpack2(a0[p]), c1 = unpack2(a1[p]);
                float2 c2 = unpack2(a2[p]), c3 = unpack2(a3[p]);
                float v0 = (par ? c0.y : c0.x) + xa.x + xb.x;
                float v1 = (par ? c1.y : c1.x) + xa.y + xb.y;
                float v2 = (par ? c2.y : c2.x) + xa.z + xb.z;
                float v3 = (par ? c3.y : c3.x) + xa.w + xb.w;
                v0 = v0 > 0.0f ? v0 : __expf(v0) - 1.0f;
                v1 = v1 > 0.0f ? v1 : __expf(v1) - 1.0f;
                v2 = v2 > 0.0f ? v2 : __expf(v2) - 1.0f;
                v3 = v3 > 0.0f ? v3 : __expf(v3) - 1.0f;
                float msk = (sEaF[e] < 8.0f) ? 1.0f : 0.0f;
                v0 *= msk; v1 *= msk; v2 *= msk; v3 *= msk;
                fv[i][0] = v0; fv[i][1] = v1; fv[i][2] = v2; fv[i][3] = v3;
                pd[i] = v0*xm.x + v1*xm.y + v2*xm.z + v3*xm.w;
            }
            #pragma unroll
            for (int off = 16; off; off >>= 1) {
                #pragma unroll
                for (int i = 0; i < 4; i++)
                    pd[i] += __shfl_xor_sync(0xffffffffu, pd[i], off);
            }
            float av[4], sc[4];
            #pragma unroll
            for (int i = 0; i < 4; i++) {
                av[i] = tanh_fast(pd[i]);
                sc[i] = __expf(av[i]);
            }
            #pragma unroll
            for (int i = 0; i < 4; i++) {
                asm volatile("red.global.add.v4.f32 [%0], {%1, %2, %3, %4};"
                             :: "l"(g_aggr + (size_t)sg[i]*C + 4*lane),
                                "f"(sc[i]*fv[i][0]), "f"(sc[i]*fv[i][1]),
                                "f"(sc[i]*fv[i][2]), "f"(sc[i]*fv[i][3])
                             : "memory");
                if (lane == 0) atomicAdd(&g_asum[sg[i]], av[i]);
            }
        }
    }
}

// ---------------- K4: out = (x + exp(-asum)*aggr) @ Wu + bu ------------------
__global__ __launch_bounds__(256, 5) void node_out_kernel(const float* __restrict__ x,
                                                          const float* __restrict__ Wu,
                                                          const float* __restrict__ bu,
                                                          float* __restrict__ out) {
    extern __shared__ unsigned char smem[];
    float4*     sW4  = (float4*)(smem + NODE_SW);
    ulonglong2* sWu2 = (ulonglong2*)(smem + NODE_SW);
    float*      sXf  = (float*)(smem + NODE_SX);
    float*      sDsc = (float*)(smem + NODE_SD);
    int tid = threadIdx.x, lane = tid & 31, w = tid >> 5;
    const float4* W4 = (const float4*)Wu;
    float4 b4 = *(const float4*)(bu + 4*lane);
    ull bi0 = pack2(b4.x, b4.y), bi1 = pack2(b4.z, b4.w);
    const int ntiles = (NN + 31) / 32;
    for (int h = 0; h < 2; h++) {
        __syncthreads();
        for (int i = tid; i < 64*32; i += 256) {
            int dd = i >> 5, l = i & 31;
            sW4[i] = W4[(h*64 + dd)*32 + l];
        }
        for (int tile = blockIdx.x; tile < ntiles; tile += gridDim.x) {
            int n0 = tile * 32;
            __syncthreads();
            if (tid < 32) {
                int ng = n0 + tid;
                sDsc[tid] = (ng < NN) ? __expf(-g_asum[ng]) : 0.0f;
            }
            __syncthreads();
            for (int i = tid; i < 64*32; i += 256) {
                int d = i & 63, n = i >> 6, ng = n0 + n;
                float v = 0.0f;
                if (ng < NN) {
                    size_t off = (size_t)ng*C + h*64 + d;
                    v = x[off] + sDsc[n] * g_aggr[off];
                }
                sXf[d*33 + n] = v;
            }
            __syncthreads();
            int nb = w * 4;
            ull a0[4], a1[4];
            #pragma unroll
            for (int e = 0; e < 4; e++) {
                a0[e] = h ? 0ull : bi0;
                a1[e] = h ? 0ull : bi1;
            }
            node_gemm_half(sXf, sWu2, lane, nb, a0, a1);
            #pragma unroll 1
            for (int e = 0; e < 4; e++) {
                int n = n0 + nb + e;
                if (n < NN) {
                    float2 f0 = unpack2(a0[e]), f1 = unpack2(a1[e]);
                    float4 o; o.x = f0.x; o.y = f0.y; o.z = f1.x; o.w = f1.y;
                    float* yp = out + (size_t)n*C + 4*lane;
                    if (h) {
                        float4 prev = *(float4*)yp;
                        o.x += prev.x; o.y += prev.y; o.z += prev.z; o.w += prev.w;
                    }
                    *(float4*)yp = o;
                }
            }
        }
    }
}

// ---------------- host launcher ----------------------------------------------
extern "C" void kernel_launch(void* const* d_in, const int* in_sizes, int n_in,
                              void* d_out, int out_size) {
    const float* x   = (const float*)d_in[0];
    const int*   ei  = (const int*  )d_in[1];
    const float* ea  = (const float*)d_in[2];
    const float* Wf  = (const float*)d_in[3];
    const float* bf  = (const float*)d_in[4];
    const float* Wq  = (const float*)d_in[5];
    const float* Wk  = (const float*)d_in[6];
    const float* Wa  = (const float*)d_in[7];
    const float* Wu  = (const float*)d_in[8];
    const float* bu  = (const float*)d_in[9];
    float* out = (float*)d_out;

    (void)in_sizes; (void)n_in; (void)out_size;

    cudaFuncSetAttribute(node_pre_kernel, cudaFuncAttributeMaxDynamicSharedMemorySize, NODE_SMEM);
    cudaFuncSetAttribute(node_out_kernel, cudaFuncAttributeMaxDynamicSharedMemorySize, NODE_SMEM);
    cudaFuncSetAttribute(edge1_kernel,    cudaFuncAttributeMaxDynamicSharedMemorySize, E1_SMEM);

    prep_kernel<<<C, C>>>(Wf, Wq, Wk, Wa);
    node_pre_kernel<<<740, 256, NODE_SMEM>>>(x);
    edge1_kernel<<<592, 256, E1_SMEM>>>(ea, ei, Wf, bf);
    node_out_kernel<<<740, 256, NODE_SMEM>>>(x, Wu, bu, out);
}

// round 16
// speedup vs baseline: 1.0607x; 1.0607x over previous
#include <cuda_runtime.h>

#define NN   50000
#define C    128
#define E    800000
#define EF   65
#define EAC  70
#define ET   64

typedef unsigned long long ull;

// ---------------- scratch (device globals; no allocation allowed) ------------
__device__ float g_A [C*C];           // Wf1 + Wf3
__device__ float g_B [C*C];           // Wf2 - Wf3
__device__ float g_M [C*C];           // scale * Wq diag(Wa) Wk^T
__device__ float g_XA[NN*C];          // x @ A
__device__ float g_XB[NN*C];          // x @ B
__device__ float g_Xm[NN*C];          // x @ M
__device__ float g_asum[NN];          // segment sum of a over src
__device__ float g_aggr[NN*C];        // segment sum of exp(a)*f over src

// ---------------- packed fp32x2 helpers (Blackwell FFMA2) --------------------
__device__ __forceinline__ void fma2(ull &acc, ull a, ull b) {
    asm("fma.rn.f32x2 %0, %1, %2, %0;" : "+l"(acc) : "l"(a), "l"(b));
}
__device__ __forceinline__ ull dup2(float v) {
    unsigned int u = __float_as_uint(v);
    return ((ull)u << 32) | (ull)u;
}
__device__ __forceinline__ ull pack2(float x, float y) {
    return ((ull)__float_as_uint(y) << 32) | (ull)__float_as_uint(x);
}
__device__ __forceinline__ float2 unpack2(ull p) {
    float2 r;
    r.x = __uint_as_float((unsigned int)(p & 0xffffffffull));
    r.y = __uint_as_float((unsigned int)(p >> 32));
    return r;
}
// tanh via exp, saturates correctly at +-1
__device__ __forceinline__ float tanh_fast(float x) {
    float t = __expf(2.0f * x);
    return 1.0f - __fdividef(2.0f, t + 1.0f);
}

// ---------------- K0: fold weights ------------------------------------------
__global__ void prep_kernel(const float* __restrict__ Wf, const float* __restrict__ Wq,
                            const float* __restrict__ Wk, const float* __restrict__ Wa) {
    int d = blockIdx.x;      // 0..127
    int c = threadIdx.x;     // 0..127
    g_A[d*C + c] = Wf[d*C + c]        + Wf[(256+d)*C + c];
    g_B[d*C + c] = Wf[(128+d)*C + c]  - Wf[(256+d)*C + c];
    __shared__ float sWa[C], sWq[C];
    sWa[c] = Wa[c];
    sWq[c] = Wq[d*C + c];
    __syncthreads();
    float acc = 0.0f;
    #pragma unroll 4
    for (int k = 0; k < C; k++) acc += sWq[k] * sWa[k] * Wk[c*C + k];
    g_M[d*C + c] = acc * 0.08838834764831845f;   // 128^-0.5
}

// ============ K-split node-GEMM scheme (R13-proven) ===========================
//   sW4  [64][32] float4 @ 0      32768 B
//   sXf  [64][33] f32    @ 32768   8448 B
//   sDsc [32] f32        @ 41216    128 B   (node_out: per-node exp(-asum))
#define NODE_SW   0
#define NODE_SX   32768
#define NODE_SD   41216
#define NODE_SMEM 41344

__device__ __forceinline__ void node_gemm_half(const float* sXf, const ulonglong2* sWu2,
                                               int lane, int nb, ull a0[4], ull a1[4]) {
    #pragma unroll 8
    for (int d = 0; d < 64; d++) {
        ulonglong2 wv = sWu2[d*32 + lane];
        #pragma unroll
        for (int e = 0; e < 4; e++) {
            ull xv = dup2(sXf[d*33 + nb + e]);
            fma2(a0[e], xv, wv.x);
            fma2(a1[e], xv, wv.y);
        }
    }
}

// ---------------- K1: node precompute XA, XB, Xm (+ zero fold) ---------------
__global__ __launch_bounds__(256, 4) void node_pre_kernel(const float* __restrict__ x) {
    extern __shared__ unsigned char smem[];
    float4*     sW4  = (float4*)(smem + NODE_SW);
    ulonglong2* sWu2 = (ulonglong2*)(smem + NODE_SW);
    float*      sXf  = (float*)(smem + NODE_SX);
    int tid = threadIdx.x, lane = tid & 31, w = tid >> 5;

    // folded zero of the accumulators (no sync needed; consumed next kernel)
    {
        float4 z; z.x = 0.0f; z.y = 0.0f; z.z = 0.0f; z.w = 0.0f;
        for (int i = blockIdx.x*256 + tid; i < NN*C/4; i += gridDim.x*256)
            ((float4*)g_aggr)[i] = z;
        for (int i = blockIdx.x*256 + tid; i < NN; i += gridDim.x*256)
            g_asum[i] = 0.0f;
    }

    const float* Ws[3] = {g_A, g_B, g_M};
    float*       Ys[3] = {g_XA, g_XB, g_Xm};
    const int ntiles = (NN + 31) / 32;
    for (int m = 0; m < 3; m++) {
        const float4* W4 = (const float4*)Ws[m];
        float* Y = Ys[m];
        for (int h = 0; h < 2; h++) {
            __syncthreads();
            for (int i = tid; i < 64*32; i += 256) {
                int dd = i >> 5, l = i & 31;
                sW4[i] = W4[(h*64 + dd)*32 + l];
            }
            for (int tile = blockIdx.x; tile < ntiles; tile += gridDim.x) {
                int n0 = tile * 32;
                __syncthreads();
                for (int i = tid; i < 64*32; i += 256) {
                    int d = i & 63, n = i >> 6, ng = n0 + n;
                    sXf[d*33 + n] = (ng < NN) ? x[(size_t)ng*C + h*64 + d] : 0.0f;
                }
                __syncthreads();
                int nb = w * 4;
                ull a0[4] = {0,0,0,0}, a1[4] = {0,0,0,0};
                node_gemm_half(sXf, sWu2, lane, nb, a0, a1);
                #pragma unroll 1
                for (int e = 0; e < 4; e++) {
                    int n = n0 + nb + e;
                    if (n < NN) {
                        float2 f0 = unpack2(a0[e]), f1 = unpack2(a1[e]);
                        float4 o; o.x = f0.x; o.y = f0.y; o.z = f1.x; o.w = f1.y;
                        float* yp = Y + (size_t)n*C + 4*lane;
                        if (h) {
                            float4 prev = *(float4*)yp;
                            o.x += prev.x; o.y += prev.y; o.z += prev.z; o.w += prev.w;
                        }
                        *(float4*)yp = o;
                    }
                }
            }
        }
    }
}

// ---------------- K2: edge pass — f, a, scatter exp(a)*f and a ----------------
// 256 thr (8 warps), 64 edges/tile, warp = 8 edges (4 edge-pairs) x 128 ch.
//   sW4  [65][32] float4  @ 0      33280 B
//   sEa  [65][66] float   @ 33280  17160 B  (u64 col p = edge pair {2p,2p+1})
//   sBf4 [32]  float4     @ 50448    512 B
//   sIdx [128] int        @ 50960    512 B
#define E1_SW   0
#define E1_SEA  33280
#define E1_SBF  50448
#define E1_SIDX 50960
#define E1_SMEM 51472

__global__ __launch_bounds__(256, 4) void edge1_kernel(const float* __restrict__ ea,
                                                       const int*   __restrict__ ei,
                                                       const float* __restrict__ Wf,
                                                       const float* __restrict__ bf) {
    extern __shared__ unsigned char smem[];
    float4*     sW4  = (float4*)(smem + E1_SW);
    ull*        sEa2 = (ull*)(smem + E1_SEA);
    float*      sEaF = (float*)(smem + E1_SEA);
    float4*     sBf4 = (float4*)(smem + E1_SBF);
    int*        sIdx = (int*)(smem + E1_SIDX);
    int tid = threadIdx.x, lane = tid & 31, w = tid >> 5;

    for (int i = tid; i < EF*32; i += 256) {
        int d = i >> 5, l = i & 31;
        sW4[i] = *(const float4*)(Wf + (size_t)(3*C + d)*C + 4*l);
    }
    if (tid < 32) sBf4[tid] = *(const float4*)(bf + 4*tid);
    __syncthreads();
    float4 b4 = sBf4[lane];
    ull bi0 = dup2(b4.x), bi1 = dup2(b4.y), bi2 = dup2(b4.z), bi3 = dup2(b4.w);

    const int eb = w * 8;                 // this warp's 8 edges within the tile
    const int pb = w * 4;                 // this warp's 4 edge-pairs
    const int ntiles = E / ET;            // 12500
    for (int tile = blockIdx.x; tile < ntiles; tile += gridDim.x) {
        int e0 = tile * ET;
        __syncthreads();
        if (tid < ET)           sIdx[tid] = ei[e0 + tid];
        else if (tid < 2*ET)    sIdx[tid] = ei[E + e0 + tid - ET];
        // coalesced ea staging; lane l writes rows (l, l+32): word-stride 66
        // => 2-way STS bank conflict
        #pragma unroll 1
        for (int i = 0; i < 8; i++) {
            int e = eb + i;
            const float* row = ea + (size_t)(e0 + e)*EAC;
            float vx = __ldcs(row + lane);
            float vy = __ldcs(row + lane + 32);
            sEaF[lane*66        + e] = vx;
            sEaF[(lane + 32)*66 + e] = vy;
            if (lane == 0) sEaF[64*66 + e] = __ldcs(row + 64);
        }
        __syncthreads();

        // GEMM: acc[c][p] = f32x2 accumulator for channel 4*lane+c, edge pair p
        ull a0[4], a1[4], a2[4], a3[4];
        #pragma unroll
        for (int p = 0; p < 4; p++) { a0[p]=bi0; a1[p]=bi1; a2[p]=bi2; a3[p]=bi3; }
        #pragma unroll 5
        for (int d = 0; d < EF; d++) {
            float4 wv = sW4[d*32 + lane];
            ull w0 = dup2(wv.x), w1 = dup2(wv.y), w2 = dup2(wv.z), w3 = dup2(wv.w);
            const ull* er = sEa2 + d*33 + pb;
            #pragma unroll
            for (int p = 0; p < 4; p++) {
                ull ep = er[p];                  // LDS.64 broadcast
                fma2(a0[p], ep, w0);
                fma2(a1[p], ep, w1);
                fma2(a2[p], ep, w2);
                fma2(a3[p], ep, w3);
            }
        }

        // ---- batched epilogue: 2 groups of 4 edges --------------------------
        #pragma unroll
        for (int g = 0; g < 2; g++) {
            float fv[4][4];
            float pd[4];
            int   sg[4];
            #pragma unroll
            for (int i = 0; i < 4; i++) {
                int e = eb + g*4 + i;
                int p = (g*4 + i) >> 1, par = i & 1;
                int s = sIdx[e], t = sIdx[ET + e];
                sg[i] = s;
                float4 xa = __ldg((const float4*)(g_XA + (size_t)s*C + 4*lane));
                float4 xb = __ldg((const float4*)(g_XB + (size_t)t*C + 4*lane));
                float4 xm = __ldg((const float4*)(g_Xm + (size_t)s*C + 4*lane));
                float2 c0 = unpack2(a0[p]), c1 = unpack2(a1[p]);
                float2 c2 = unpack2(a2[p]), c3 = unpack2(a3[p]);
                float v0 = (par ? c0.y : c0.x) + xa.x + xb.x;
                float v1 = (par ? c1.y : c1.x) + xa.y + xb.y;
                float v2 = (par ? c2.y : c2.x) + xa.z + xb.z;
                float v3 = (par ? c3.y : c3.x) + xa.w + xb.w;
                v0 = v0 > 0.0f ? v0 : __expf(v0) - 1.0f;
                v1 = v1 > 0.0f ? v1 : __expf(v1) - 1.0f;
                v2 = v2 > 0.0f ? v2 : __expf(v2) - 1.0f;
                v3 = v3 > 0.0f ? v3 : __expf(v3) - 1.0f;
                float msk = (sEaF[e] < 8.0f) ? 1.0f : 0.0f;
                v0 *= msk; v1 *= msk; v2 *= msk; v3 *= msk;
                fv[i][0] = v0; fv[i][1] = v1; fv[i][2] = v2; fv[i][3] = v3;
                pd[i] = v0*xm.x + v1*xm.y + v2*xm.z + v3*xm.w;
            }
            #pragma unroll
            for (int off = 16; off; off >>= 1) {
                #pragma unroll
                for (int i = 0; i < 4; i++)
                    pd[i] += __shfl_xor_sync(0xffffffffu, pd[i], off);
            }
            float av[4], sc[4];
            #pragma unroll
            for (int i = 0; i < 4; i++) {
                av[i] = tanh_fast(pd[i]);
                sc[i] = __expf(av[i]);
            }
            #pragma unroll
            for (int i = 0; i < 4; i++) {
                asm volatile("red.global.add.v4.f32 [%0], {%1, %2, %3, %4};"
                             :: "l"(g_aggr + (size_t)sg[i]*C + 4*lane),
                                "f"(sc[i]*fv[i][0]), "f"(sc[i]*fv[i][1]),
                                "f"(sc[i]*fv[i][2]), "f"(sc[i]*fv[i][3])
                             : "memory");
                if (lane == 0) atomicAdd(&g_asum[sg[i]], av[i]);
            }
        }
    }
}

// ---------------- K4: out = (x + exp(-asum)*aggr) @ Wu + bu ------------------
__global__ __launch_bounds__(256, 4) void node_out_kernel(const float* __restrict__ x,
                                                          const float* __restrict__ Wu,
                                                          const float* __restrict__ bu,
                                                          float* __restrict__ out) {
    extern __shared__ unsigned char smem[];
    float4*     sW4  = (float4*)(smem + NODE_SW);
    ulonglong2* sWu2 = (ulonglong2*)(smem + NODE_SW);
    float*      sXf  = (float*)(smem + NODE_SX);
    float*      sDsc = (float*)(smem + NODE_SD);
    int tid = threadIdx.x, lane = tid & 31, w = tid >> 5;
    const float4* W4 = (const float4*)Wu;
    float4 b4 = *(const float4*)(bu + 4*lane);
    ull bi0 = pack2(b4.x, b4.y), bi1 = pack2(b4.z, b4.w);
    const int ntiles = (NN + 31) / 32;
    for (int h = 0; h < 2; h++) {
        __syncthreads();
        for (int i = tid; i < 64*32; i += 256) {
            int dd = i >> 5, l = i & 31;
            sW4[i] = W4[(h*64 + dd)*32 + l];
        }
        for (int tile = blockIdx.x; tile < ntiles; tile += gridDim.x) {
            int n0 = tile * 32;
            __syncthreads();
            if (tid < 32) {
                int ng = n0 + tid;
                sDsc[tid] = (ng < NN) ? __expf(-g_asum[ng]) : 0.0f;
            }
            __syncthreads();
            for (int i = tid; i < 64*32; i += 256) {
                int d = i & 63, n = i >> 6, ng = n0 + n;
                float v = 0.0f;
                if (ng < NN) {
                    size_t off = (size_t)ng*C + h*64 + d;
                    v = x[off] + sDsc[n] * g_aggr[off];
                }
                sXf[d*33 + n] = v;
            }
            __syncthreads();
            int nb = w * 4;
            ull a0[4], a1[4];
            #pragma unroll
            for (int e = 0; e < 4; e++) {
                a0[e] = h ? 0ull : bi0;
                a1[e] = h ? 0ull : bi1;
            }
            node_gemm_half(sXf, sWu2, lane, nb, a0, a1);
            #pragma unroll 1
            for (int e = 0; e < 4; e++) {
                int n = n0 + nb + e;
                if (n < NN) {
                    float2 f0 = unpack2(a0[e]), f1 = unpack2(a1[e]);
                    float4 o; o.x = f0.x; o.y = f0.y; o.z = f1.x; o.w = f1.y;
                    float* yp = out + (size_t)n*C + 4*lane;
                    if (h) {
                        float4 prev = *(float4*)yp;
                        o.x += prev.x; o.y += prev.y; o.z += prev.z; o.w += prev.w;
                    }
                    *(float4*)yp = o;
                }
            }
        }
    }
}

// ---------------- host launcher ----------------------------------------------
extern "C" void kernel_launch(void* const* d_in, const int* in_sizes, int n_in,
                              void* d_out, int out_size) {
    const float* x   = (const float*)d_in[0];
    const int*   ei  = (const int*  )d_in[1];
    const float* ea  = (const float*)d_in[2];
    const float* Wf  = (const float*)d_in[3];
    const float* bf  = (const float*)d_in[4];
    const float* Wq  = (const float*)d_in[5];
    const float* Wk  = (const float*)d_in[6];
    const float* Wa  = (const float*)d_in[7];
    const float* Wu  = (const float*)d_in[8];
    const float* bu  = (const float*)d_in[9];
    float* out = (float*)d_out;

    (void)in_sizes; (void)n_in; (void)out_size;

    cudaFuncSetAttribute(node_pre_kernel, cudaFuncAttributeMaxDynamicSharedMemorySize, NODE_SMEM);
    cudaFuncSetAttribute(node_out_kernel, cudaFuncAttributeMaxDynamicSharedMemorySize, NODE_SMEM);
    cudaFuncSetAttribute(edge1_kernel,    cudaFuncAttributeMaxDynamicSharedMemorySize, E1_SMEM);

    prep_kernel<<<C, C>>>(Wf, Wq, Wk, Wa);
    node_pre_kernel<<<592, 256, NODE_SMEM>>>(x);
    edge1_kernel<<<592, 256, E1_SMEM>>>(ea, ei, Wf, bf);
    node_out_kernel<<<592, 256, NODE_SMEM>>>(x, Wu, bu, out);
}

// round 17
// speedup vs baseline: 1.0842x; 1.0221x over previous
#include <cuda_runtime.h>

#define NN   50000
#define C    128
#define E    800000
#define EF   65
#define EAC  70
#define ET   64

typedef unsigned long long ull;

// ---------------- scratch (device globals; no allocation allowed) ------------
__device__ float g_A [C*C];           // Wf1 + Wf3
__device__ float g_B [C*C];           // Wf2 - Wf3
__device__ float g_M [C*C];           // scale * Wq diag(Wa) Wk^T
__device__ float g_XA[NN*C];          // x @ A
__device__ float g_XB[NN*C];          // x @ B
__device__ float g_Xm[NN*C];          // x @ M
__device__ float g_asum[NN];          // segment sum of a over src
__device__ float g_aggr[NN*C];        // segment sum of exp(a)*f over src

// ---------------- packed fp32x2 helpers (Blackwell FFMA2) --------------------
__device__ __forceinline__ void fma2(ull &acc, ull a, ull b) {
    asm("fma.rn.f32x2 %0, %1, %2, %0;" : "+l"(acc) : "l"(a), "l"(b));
}
__device__ __forceinline__ ull dup2(float v) {
    unsigned int u = __float_as_uint(v);
    return ((ull)u << 32) | (ull)u;
}
__device__ __forceinline__ ull pack2(float x, float y) {
    return ((ull)__float_as_uint(y) << 32) | (ull)__float_as_uint(x);
}
__device__ __forceinline__ float2 unpack2(ull p) {
    float2 r;
    r.x = __uint_as_float((unsigned int)(p & 0xffffffffull));
    r.y = __uint_as_float((unsigned int)(p >> 32));
    return r;
}
// tanh via exp, saturates correctly at +-1
__device__ __forceinline__ float tanh_fast(float x) {
    float t = __expf(2.0f * x);
    return 1.0f - __fdividef(2.0f, t + 1.0f);
}

// ---------------- K0: fold weights ------------------------------------------
__global__ void prep_kernel(const float* __restrict__ Wf, const float* __restrict__ Wq,
                            const float* __restrict__ Wk, const float* __restrict__ Wa) {
    int d = blockIdx.x;      // 0..127
    int c = threadIdx.x;     // 0..127
    g_A[d*C + c] = Wf[d*C + c]        + Wf[(256+d)*C + c];
    g_B[d*C + c] = Wf[(128+d)*C + c]  - Wf[(256+d)*C + c];
    __shared__ float sWa[C], sWq[C];
    sWa[c] = Wa[c];
    sWq[c] = Wq[d*C + c];
    __syncthreads();
    float acc = 0.0f;
    #pragma unroll 4
    for (int k = 0; k < C; k++) acc += sWq[k] * sWa[k] * Wk[c*C + k];
    g_M[d*C + c] = acc * 0.08838834764831845f;   // 128^-0.5
}

// ============ K-split node-GEMM scheme (R13-proven) ===========================
//   sW4  [64][32] float4 @ 0      32768 B
//   sXf  [64][33] f32    @ 32768   8448 B
//   sDsc [32] f32        @ 41216    128 B   (node_out: per-node exp(-asum))
#define NODE_SW   0
#define NODE_SX   32768
#define NODE_SD   41216
#define NODE_SMEM 41344

__device__ __forceinline__ void node_gemm_half(const float* sXf, const ulonglong2* sWu2,
                                               int lane, int nb, ull a0[4], ull a1[4]) {
    #pragma unroll 8
    for (int d = 0; d < 64; d++) {
        ulonglong2 wv = sWu2[d*32 + lane];
        #pragma unroll
        for (int e = 0; e < 4; e++) {
            ull xv = dup2(sXf[d*33 + nb + e]);
            fma2(a0[e], xv, wv.x);
            fma2(a1[e], xv, wv.y);
        }
    }
}

// ---------------- K1: node precompute XA, XB, Xm (+ zero fold) ---------------
__global__ __launch_bounds__(256, 4) void node_pre_kernel(const float* __restrict__ x) {
    extern __shared__ unsigned char smem[];
    float4*     sW4  = (float4*)(smem + NODE_SW);
    ulonglong2* sWu2 = (ulonglong2*)(smem + NODE_SW);
    float*      sXf  = (float*)(smem + NODE_SX);
    int tid = threadIdx.x, lane = tid & 31, w = tid >> 5;

    // folded zero of the accumulators (no sync needed; consumed next kernel)
    {
        float4 z; z.x = 0.0f; z.y = 0.0f; z.z = 0.0f; z.w = 0.0f;
        for (int i = blockIdx.x*256 + tid; i < NN*C/4; i += gridDim.x*256)
            ((float4*)g_aggr)[i] = z;
        for (int i = blockIdx.x*256 + tid; i < NN; i += gridDim.x*256)
            g_asum[i] = 0.0f;
    }

    const float* Ws[3] = {g_A, g_B, g_M};
    float*       Ys[3] = {g_XA, g_XB, g_Xm};
    const int ntiles = (NN + 31) / 32;
    for (int m = 0; m < 3; m++) {
        const float4* W4 = (const float4*)Ws[m];
        float* Y = Ys[m];
        for (int h = 0; h < 2; h++) {
            __syncthreads();
            for (int i = tid; i < 64*32; i += 256) {
                int dd = i >> 5, l = i & 31;
                sW4[i] = W4[(h*64 + dd)*32 + l];
            }
            for (int tile = blockIdx.x; tile < ntiles; tile += gridDim.x) {
                int n0 = tile * 32;
                __syncthreads();
                for (int i = tid; i < 64*32; i += 256) {
                    int d = i & 63, n = i >> 6, ng = n0 + n;
                    sXf[d*33 + n] = (ng < NN) ? x[(size_t)ng*C + h*64 + d] : 0.0f;
                }
                __syncthreads();
                int nb = w * 4;
                ull a0[4] = {0,0,0,0}, a1[4] = {0,0,0,0};
                node_gemm_half(sXf, sWu2, lane, nb, a0, a1);
                #pragma unroll 1
                for (int e = 0; e < 4; e++) {
                    int n = n0 + nb + e;
                    if (n < NN) {
                        float2 f0 = unpack2(a0[e]), f1 = unpack2(a1[e]);
                        float4 o; o.x = f0.x; o.y = f0.y; o.z = f1.x; o.w = f1.y;
                        float* yp = Y + (size_t)n*C + 4*lane;
                        if (h) {
                            float4 prev = *(float4*)yp;
                            o.x += prev.x; o.y += prev.y; o.z += prev.z; o.w += prev.w;
                        }
                        *(float4*)yp = o;
                    }
                }
            }
        }
    }
}

// ---------------- K2: edge pass — f, a, scatter exp(a)*f and a ----------------
// 256 thr (8 warps), 64 edges/tile, warp = 8 edges (4 edge-pairs) x 128 ch.
//   sW4  [65][32] float4  @ 0      33280 B
//   sEa  [65][66] float   @ 33280  17160 B  (u64 col p = edge pair {2p,2p+1})
//   sBf4 [32]  float4     @ 50448    512 B
//   sIdx [128] int        @ 50960    512 B
#define E1_SW   0
#define E1_SEA  33280
#define E1_SBF  50448
#define E1_SIDX 50960
#define E1_SMEM 51472

__global__ __launch_bounds__(256, 4) void edge1_kernel(const float* __restrict__ ea,
                                                       const int*   __restrict__ ei,
                                                       const float* __restrict__ Wf,
                                                       const float* __restrict__ bf) {
    extern __shared__ unsigned char smem[];
    float4*     sW4  = (float4*)(smem + E1_SW);
    ull*        sEa2 = (ull*)(smem + E1_SEA);
    float*      sEaF = (float*)(smem + E1_SEA);
    float4*     sBf4 = (float4*)(smem + E1_SBF);
    int*        sIdx = (int*)(smem + E1_SIDX);
    int tid = threadIdx.x, lane = tid & 31, w = tid >> 5;

    for (int i = tid; i < EF*32; i += 256) {
        int d = i >> 5, l = i & 31;
        sW4[i] = *(const float4*)(Wf + (size_t)(3*C + d)*C + 4*l);
    }
    if (tid < 32) sBf4[tid] = *(const float4*)(bf + 4*tid);
    __syncthreads();
    float4 b4 = sBf4[lane];
    ull bi0 = dup2(b4.x), bi1 = dup2(b4.y), bi2 = dup2(b4.z), bi3 = dup2(b4.w);

    const int eb = w * 8;                 // this warp's 8 edges within the tile
    const int pb = w * 4;                 // this warp's 4 edge-pairs
    const int ntiles = E / ET;            // 12500
    for (int tile = blockIdx.x; tile < ntiles; tile += gridDim.x) {
        int e0 = tile * ET;
        __syncthreads();
        if (tid < ET)           sIdx[tid] = ei[e0 + tid];
        else if (tid < 2*ET)    sIdx[tid] = ei[E + e0 + tid - ET];
        // batched ea staging: phase A = 17 independent streaming loads (MLP~17),
        // phase B = stores. lane l owns rows (l, l+32): word-stride 66 => 2-way STS.
        {
            float vx[8], vy[8], vt[8];
            const float* rbase = ea + (size_t)(e0 + eb)*EAC;
            #pragma unroll
            for (int i = 0; i < 8; i++) {
                const float* row = rbase + (size_t)i*EAC;
                vx[i] = __ldcs(row + lane);
                vy[i] = __ldcs(row + lane + 32);
            }
            if (lane == 0) {
                #pragma unroll
                for (int i = 0; i < 8; i++)
                    vt[i] = __ldcs(rbase + (size_t)i*EAC + 64);
            }
            #pragma unroll
            for (int i = 0; i < 8; i++) {
                sEaF[lane*66        + eb + i] = vx[i];
                sEaF[(lane + 32)*66 + eb + i] = vy[i];
            }
            if (lane == 0) {
                #pragma unroll
                for (int i = 0; i < 8; i++)
                    sEaF[64*66 + eb + i] = vt[i];
            }
        }
        __syncthreads();

        // GEMM: acc[c][p] = f32x2 accumulator for channel 4*lane+c, edge pair p
        ull a0[4], a1[4], a2[4], a3[4];
        #pragma unroll
        for (int p = 0; p < 4; p++) { a0[p]=bi0; a1[p]=bi1; a2[p]=bi2; a3[p]=bi3; }
        #pragma unroll 5
        for (int d = 0; d < EF; d++) {
            float4 wv = sW4[d*32 + lane];
            ull w0 = dup2(wv.x), w1 = dup2(wv.y), w2 = dup2(wv.z), w3 = dup2(wv.w);
            const ull* er = sEa2 + d*33 + pb;
            #pragma unroll
            for (int p = 0; p < 4; p++) {
                ull ep = er[p];                  // LDS.64 broadcast
                fma2(a0[p], ep, w0);
                fma2(a1[p], ep, w1);
                fma2(a2[p], ep, w2);
                fma2(a3[p], ep, w3);
            }
        }

        // ---- batched epilogue: 2 groups of 4 edges --------------------------
        #pragma unroll
        for (int g = 0; g < 2; g++) {
            float fv[4][4];
            float pd[4];
            int   sg[4];
            #pragma unroll
            for (int i = 0; i < 4; i++) {
                int e = eb + g*4 + i;
                int p = (g*4 + i) >> 1, par = i & 1;
                int s = sIdx[e], t = sIdx[ET + e];
                sg[i] = s;
                float4 xa = __ldg((const float4*)(g_XA + (size_t)s*C + 4*lane));
                float4 xb = __ldg((const float4*)(g_XB + (size_t)t*C + 4*lane));
                float4 xm = __ldg((const float4*)(g_Xm + (size_t)s*C + 4*lane));
                float2 c0 = unpack2(a0[p]), c1 = unpack2(a1[p]);
                float2 c2 = unpack2(a2[p]), c3 = unpack2(a3[p]);
                float v0 = (par ? c0.y : c0.x) + xa.x + xb.x;
                float v1 = (par ? c1.y : c1.x) + xa.y + xb.y;
                float v2 = (par ? c2.y : c2.x) + xa.z + xb.z;
                float v3 = (par ? c3.y : c3.x) + xa.w + xb.w;
                v0 = v0 > 0.0f ? v0 : __expf(v0) - 1.0f;
                v1 = v1 > 0.0f ? v1 : __expf(v1) - 1.0f;
                v2 = v2 > 0.0f ? v2 : __expf(v2) - 1.0f;
                v3 = v3 > 0.0f ? v3 : __expf(v3) - 1.0f;
                float msk = (sEaF[e] < 8.0f) ? 1.0f : 0.0f;
                v0 *= msk; v1 *= msk; v2 *= msk; v3 *= msk;
                fv[i][0] = v0; fv[i][1] = v1; fv[i][2] = v2; fv[i][3] = v3;
                pd[i] = v0*xm.x + v1*xm.y + v2*xm.z + v3*xm.w;
            }
            #pragma unroll
            for (int off = 16; off; off >>= 1) {
                #pragma unroll
                for (int i = 0; i < 4; i++)
                    pd[i] += __shfl_xor_sync(0xffffffffu, pd[i], off);
            }
            float av[4], sc[4];
            #pragma unroll
            for (int i = 0; i < 4; i++) {
                av[i] = tanh_fast(pd[i]);
                sc[i] = __expf(av[i]);
            }
            #pragma unroll
            for (int i = 0; i < 4; i++) {
                asm volatile("red.global.add.v4.f32 [%0], {%1, %2, %3, %4};"
                             :: "l"(g_aggr + (size_t)sg[i]*C + 4*lane),
                                "f"(sc[i]*fv[i][0]), "f"(sc[i]*fv[i][1]),
                                "f"(sc[i]*fv[i][2]), "f"(sc[i]*fv[i][3])
                             : "memory");
                if (lane == 0) atomicAdd(&g_asum[sg[i]], av[i]);
            }
        }
    }
}

// ---------------- K4: out = (x + exp(-asum)*aggr) @ Wu + bu ------------------
__global__ __launch_bounds__(256, 4) void node_out_kernel(const float* __restrict__ x,
                                                          const float* __restrict__ Wu,
                                                          const float* __restrict__ bu,
                                                          float* __restrict__ out) {
    extern __shared__ unsigned char smem[];
    float4*     sW4  = (float4*)(smem + NODE_SW);
    ulonglong2* sWu2 = (ulonglong2*)(smem + NODE_SW);
    float*      sXf  = (float*)(smem + NODE_SX);
    float*      sDsc = (float*)(smem + NODE_SD);
    int tid = threadIdx.x, lane = tid & 31, w = tid >> 5;
    const float4* W4 = (const float4*)Wu;
    float4 b4 = *(const float4*)(bu + 4*lane);
    ull bi0 = pack2(b4.x, b4.y), bi1 = pack2(b4.z, b4.w);
    const int ntiles = (NN + 31) / 32;
    for (int h = 0; h < 2; h++) {
        __syncthreads();
        for (int i = tid; i < 64*32; i += 256) {
            int dd = i >> 5, l = i & 31;
            sW4[i] = W4[(h*64 + dd)*32 + l];
        }
        for (int tile = blockIdx.x; tile < ntiles; tile += gridDim.x) {
            int n0 = tile * 32;
            __syncthreads();
            if (tid < 32) {
                int ng = n0 + tid;
                sDsc[tid] = (ng < NN) ? __expf(-g_asum[ng]) : 0.0f;
            }
            __syncthreads();
            for (int i = tid; i < 64*32; i += 256) {
                int d = i & 63, n = i >> 6, ng = n0 + n;
                float v = 0.0f;
                if (ng < NN) {
                    size_t off = (size_t)ng*C + h*64 + d;
                    v = x[off] + sDsc[n] * g_aggr[off];
                }
                sXf[d*33 + n] = v;
            }
            __syncthreads();
            int nb = w * 4;
            ull a0[4], a1[4];
            #pragma unroll
            for (int e = 0; e < 4; e++) {
                a0[e] = h ? 0ull : bi0;
                a1[e] = h ? 0ull : bi1;
            }
            node_gemm_half(sXf, sWu2, lane, nb, a0, a1);
            #pragma unroll 1
            for (int e = 0; e < 4; e++) {
                int n = n0 + nb + e;
                if (n < NN) {
                    float2 f0 = unpack2(a0[e]), f1 = unpack2(a1[e]);
                    float4 o; o.x = f0.x; o.y = f0.y; o.z = f1.x; o.w = f1.y;
                    float* yp = out + (size_t)n*C + 4*lane;
                    if (h) {
                        float4 prev = *(float4*)yp;
                        o.x += prev.x; o.y += prev.y; o.z += prev.z; o.w += prev.w;
                    }
                    *(float4*)yp = o;
                }
            }
        }
    }
}

// ---------------- host launcher ----------------------------------------------
extern "C" void kernel_launch(void* const* d_in, const int* in_sizes, int n_in,
                              void* d_out, int out_size) {
    const float* x   = (const float*)d_in[0];
    const int*   ei  = (const int*  )d_in[1];
    const float* ea  = (const float*)d_in[2];
    const float* Wf  = (const float*)d_in[3];
    const float* bf  = (const float*)d_in[4];
    const float* Wq  = (const float*)d_in[5];
    const float* Wk  = (const float*)d_in[6];
    const float* Wa  = (const float*)d_in[7];
    const float* Wu  = (const float*)d_in[8];
    const float* bu  = (const float*)d_in[9];
    float* out = (float*)d_out;

    (void)in_sizes; (void)n_in; (void)out_size;

    cudaFuncSetAttribute(node_pre_kernel, cudaFuncAttributeMaxDynamicSharedMemorySize, NODE_SMEM);
    cudaFuncSetAttribute(node_out_kernel, cudaFuncAttributeMaxDynamicSharedMemorySize, NODE_SMEM);
    cudaFuncSetAttribute(edge1_kernel,    cudaFuncAttributeMaxDynamicSharedMemorySize, E1_SMEM);

    prep_kernel<<<C, C>>>(Wf, Wq, Wk, Wa);
    node_pre_kernel<<<592, 256, NODE_SMEM>>>(x);
    edge1_kernel<<<592, 256, E1_SMEM>>>(ea, ei, Wf, bf);
    node_out_kernel<<<592, 256, NODE_SMEM>>>(x, Wu, bu, out);
}